// round 12
// baseline (speedup 1.0000x reference)
#include <cuda_runtime.h>
#include <math.h>

#define BOUND        1.0f
#define MIN_NEAR     0.2f
#define T_THRESH     1e-4f
#define BG_COLOR     1.0f
#define N_STEPS      128

// One warp per ray. Lane l owns samples 4l..4l+3 (lane-contiguous float4
// addresses -> 512B coalesced per LDG.128; load pattern proven optimal R3/R5,
// all loads up-front proven necessary R8). Streaming loads (__ldcs), fast
// divides, difference-form weights, exclusive prefix via p/tot (no shuffle).
// Plain 5-value butterfly epilogue (R6/R10 alternatives regressed).
// R12: 512-thread blocks + streaming stores; body unchanged from best (R11).
__global__ __launch_bounds__(512)
void nerf_composite_kernel(const float* __restrict__ rays_o,
                           const float* __restrict__ rays_d,
                           const float* __restrict__ sigmas,
                           const float* __restrict__ rgbs,
                           float* __restrict__ out,
                           int N)
{
    const unsigned FULL = 0xFFFFFFFFu;
    int w    = (blockIdx.x * blockDim.x + threadIdx.x) >> 5;
    int lane = threadIdx.x & 31;
    if (w >= N) return;
    const int r = w;

    // ---- 4 coalesced streaming LDG.128 per lane, all independent ----
    const float4* sig4 = (const float4*)(sigmas + (size_t)r * N_STEPS);
    const float4* rgb4 = (const float4*)(rgbs   + (size_t)r * (N_STEPS * 3));

    float4 s4 = __ldcs(&sig4[lane]);
    float4 c0 = __ldcs(&rgb4[3 * lane + 0]);
    float4 c1 = __ldcs(&rgb4[3 * lane + 1]);
    float4 c2 = __ldcs(&rgb4[3 * lane + 2]);
    // sample 0: (c0.x c0.y c0.z)  sample 1: (c0.w c1.x c1.y)
    // sample 2: (c1.z c1.w c2.x)  sample 3: (c2.y c2.z c2.w)

    // ---- slab test (fast divides; overlaps the loads) ----
    float ox = rays_o[3 * r + 0], oy = rays_o[3 * r + 1], oz = rays_o[3 * r + 2];
    float dx = rays_d[3 * r + 0], dy = rays_d[3 * r + 1], dz = rays_d[3 * r + 2];
    if (fabsf(dx) < 1e-8f) dx = 1e-8f;
    if (fabsf(dy) < 1e-8f) dy = 1e-8f;
    if (fabsf(dz) < 1e-8f) dz = 1e-8f;

    float t1x = __fdividef(-BOUND - ox, dx), t2x = __fdividef(BOUND - ox, dx);
    float t1y = __fdividef(-BOUND - oy, dy), t2y = __fdividef(BOUND - oy, dy);
    float t1z = __fdividef(-BOUND - oz, dz), t2z = __fdividef(BOUND - oz, dz);

    float nearv = fmaxf(fmaxf(fminf(t1x, t2x), fminf(t1y, t2y)), fminf(t1z, t2z));
    float farv  = fminf(fminf(fmaxf(t1x, t2x), fmaxf(t1y, t2y)), fmaxf(t1z, t2z));
    nearv = fmaxf(nearv, MIN_NEAR);
    farv  = fmaxf(farv, nearv + 1e-4f);

    const float delta = (farv - nearv) * (1.0f / (float)N_STEPS);
    const float nd = -delta;

    // ---- survival values (eps kept to match reference cumprod) ----
    float v0 = __expf(s4.x * nd) + 1e-10f;
    float v1 = __expf(s4.y * nd) + 1e-10f;
    float v2 = __expf(s4.z * nd) + 1e-10f;
    float v3 = __expf(s4.w * nd) + 1e-10f;

    // lane-local prefix products
    float lp1 = v0;
    float lp2 = v0 * v1;
    float lp3 = lp2 * v2;
    float tot = lp3 * v3;

    // warp inclusive scan-product over lane totals
    float p = tot;
    #pragma unroll
    for (int off = 1; off < 32; off <<= 1) {
        float q = __shfl_up_sync(FULL, p, off);
        if (lane >= off) p *= q;
    }
    // exclusive prefix without a shuffle: p includes this lane's tot
    float excl = __fdividef(p, tot);

    // exclusive transmittance; weights in difference form
    float T0 = excl;
    float T1 = excl * lp1;
    float T2 = excl * lp2;
    float T3 = excl * lp3;
    float T4 = p;

    float w0 = (T0 > T_THRESH) ? (T0 - T1) : 0.0f;
    float w1 = (T1 > T_THRESH) ? (T1 - T2) : 0.0f;
    float w2 = (T2 > T_THRESH) ? (T2 - T3) : 0.0f;
    float w3 = (T3 > T_THRESH) ? (T3 - T4) : 0.0f;

    // ---- accumulate (depth factored) ----
    float wsum = (w0 + w1) + (w2 + w3);
    float k = fmaf(2.0f, w2, w1);
    k = fmaf(3.0f, w3, k);
    float tbase = fmaf((float)(4 * lane) + 0.5f, delta, nearv);
    float wt = fmaf(delta, k, tbase * wsum);

    float wr = w0 * c0.x; wr = fmaf(w1, c0.w, wr); wr = fmaf(w2, c1.z, wr); wr = fmaf(w3, c2.y, wr);
    float wg = w0 * c0.y; wg = fmaf(w1, c1.x, wg); wg = fmaf(w2, c1.w, wg); wg = fmaf(w3, c2.z, wg);
    float wb = w0 * c0.z; wb = fmaf(w1, c1.y, wb); wb = fmaf(w2, c2.x, wb); wb = fmaf(w3, c2.w, wb);

    // ---- 5-value butterfly reduction ----
    #pragma unroll
    for (int off = 16; off > 0; off >>= 1) {
        wsum += __shfl_xor_sync(FULL, wsum, off);
        wt   += __shfl_xor_sync(FULL, wt,   off);
        wr   += __shfl_xor_sync(FULL, wr,   off);
        wg   += __shfl_xor_sync(FULL, wg,   off);
        wb   += __shfl_xor_sync(FULL, wb,   off);
    }

    // ---- lanes 0-4 each write one output (streaming stores) ----
    if (lane < 5) {
        if (lane < 3) {
            float bg = (1.0f - wsum) * BG_COLOR;
            float ch = (lane == 0) ? wr : ((lane == 1) ? wg : wb);
            __stcs(&out[3 * r + lane], ch + bg);               // image r/g/b
        } else if (lane == 3) {
            __stcs(&out[(size_t)3 * N + r], wt);               // depth
        } else {
            __stcs(&out[(size_t)4 * N + r],
                   fmaxf(wt - nearv, 0.0f) / (farv - nearv));  // depth_normalized
        }
    }
}

extern "C" void kernel_launch(void* const* d_in, const int* in_sizes, int n_in,
                              void* d_out, int out_size)
{
    const float* rays_o = (const float*)d_in[0];
    const float* rays_d = (const float*)d_in[1];
    const float* sigmas = (const float*)d_in[2];
    const float* rgbs   = (const float*)d_in[3];
    float* out = (float*)d_out;

    int N = in_sizes[0] / 3;   // rays_o is [N,3]

    // one warp per ray; 16 warps (512 threads) per block
    int warps_per_block = 512 / 32;
    int blocks = (N + warps_per_block - 1) / warps_per_block;
    nerf_composite_kernel<<<blocks, 512>>>(rays_o, rays_d, sigmas, rgbs, out, N);
}

// round 13
// speedup vs baseline: 1.0008x; 1.0008x over previous
#include <cuda_runtime.h>
#include <math.h>

#define BOUND        1.0f
#define MIN_NEAR     0.2f
#define T_THRESH     1e-4f
#define BG_COLOR     1.0f
#define N_STEPS      128

// FINAL (R11 configuration — session best, 82.66us).
// One warp per ray. Lane l owns samples 4l..4l+3 (lane-contiguous float4
// addresses -> 512B coalesced per LDG.128; load pattern proven optimal R3/R5,
// all loads up-front proven necessary R8). Streaming loads (__ldcs), fast
// divides, difference-form weights w_i = T_i - T_{i+1}, exclusive prefix via
// p/tot (no extra shuffle). Plain 5-value butterfly epilogue (R6/R10
// alternatives regressed). 256-thread blocks (512 regressed, R12).
__global__ __launch_bounds__(256)
void nerf_composite_kernel(const float* __restrict__ rays_o,
                           const float* __restrict__ rays_d,
                           const float* __restrict__ sigmas,
                           const float* __restrict__ rgbs,
                           float* __restrict__ out,
                           int N)
{
    const unsigned FULL = 0xFFFFFFFFu;
    int w    = (blockIdx.x * blockDim.x + threadIdx.x) >> 5;
    int lane = threadIdx.x & 31;
    if (w >= N) return;
    const int r = w;

    // ---- 4 coalesced streaming LDG.128 per lane, all independent ----
    const float4* sig4 = (const float4*)(sigmas + (size_t)r * N_STEPS);
    const float4* rgb4 = (const float4*)(rgbs   + (size_t)r * (N_STEPS * 3));

    float4 s4 = __ldcs(&sig4[lane]);
    float4 c0 = __ldcs(&rgb4[3 * lane + 0]);
    float4 c1 = __ldcs(&rgb4[3 * lane + 1]);
    float4 c2 = __ldcs(&rgb4[3 * lane + 2]);
    // sample 0: (c0.x c0.y c0.z)  sample 1: (c0.w c1.x c1.y)
    // sample 2: (c1.z c1.w c2.x)  sample 3: (c2.y c2.z c2.w)

    // ---- slab test (fast divides; overlaps the loads) ----
    float ox = rays_o[3 * r + 0], oy = rays_o[3 * r + 1], oz = rays_o[3 * r + 2];
    float dx = rays_d[3 * r + 0], dy = rays_d[3 * r + 1], dz = rays_d[3 * r + 2];
    if (fabsf(dx) < 1e-8f) dx = 1e-8f;
    if (fabsf(dy) < 1e-8f) dy = 1e-8f;
    if (fabsf(dz) < 1e-8f) dz = 1e-8f;

    float t1x = __fdividef(-BOUND - ox, dx), t2x = __fdividef(BOUND - ox, dx);
    float t1y = __fdividef(-BOUND - oy, dy), t2y = __fdividef(BOUND - oy, dy);
    float t1z = __fdividef(-BOUND - oz, dz), t2z = __fdividef(BOUND - oz, dz);

    float nearv = fmaxf(fmaxf(fminf(t1x, t2x), fminf(t1y, t2y)), fminf(t1z, t2z));
    float farv  = fminf(fminf(fmaxf(t1x, t2x), fmaxf(t1y, t2y)), fmaxf(t1z, t2z));
    nearv = fmaxf(nearv, MIN_NEAR);
    farv  = fmaxf(farv, nearv + 1e-4f);

    const float delta = (farv - nearv) * (1.0f / (float)N_STEPS);
    const float nd = -delta;

    // ---- survival values (eps kept to match reference cumprod) ----
    float v0 = __expf(s4.x * nd) + 1e-10f;
    float v1 = __expf(s4.y * nd) + 1e-10f;
    float v2 = __expf(s4.z * nd) + 1e-10f;
    float v3 = __expf(s4.w * nd) + 1e-10f;

    // lane-local prefix products
    float lp1 = v0;
    float lp2 = v0 * v1;
    float lp3 = lp2 * v2;
    float tot = lp3 * v3;

    // warp inclusive scan-product over lane totals
    float p = tot;
    #pragma unroll
    for (int off = 1; off < 32; off <<= 1) {
        float q = __shfl_up_sync(FULL, p, off);
        if (lane >= off) p *= q;
    }
    // exclusive prefix without a shuffle: p includes this lane's tot
    float excl = __fdividef(p, tot);

    // exclusive transmittance; weights in difference form
    float T0 = excl;
    float T1 = excl * lp1;
    float T2 = excl * lp2;
    float T3 = excl * lp3;
    float T4 = p;

    float w0 = (T0 > T_THRESH) ? (T0 - T1) : 0.0f;
    float w1 = (T1 > T_THRESH) ? (T1 - T2) : 0.0f;
    float w2 = (T2 > T_THRESH) ? (T2 - T3) : 0.0f;
    float w3 = (T3 > T_THRESH) ? (T3 - T4) : 0.0f;

    // ---- accumulate (depth factored) ----
    float wsum = (w0 + w1) + (w2 + w3);
    float k = fmaf(2.0f, w2, w1);
    k = fmaf(3.0f, w3, k);
    float tbase = fmaf((float)(4 * lane) + 0.5f, delta, nearv);
    float wt = fmaf(delta, k, tbase * wsum);

    float wr = w0 * c0.x; wr = fmaf(w1, c0.w, wr); wr = fmaf(w2, c1.z, wr); wr = fmaf(w3, c2.y, wr);
    float wg = w0 * c0.y; wg = fmaf(w1, c1.x, wg); wg = fmaf(w2, c1.w, wg); wg = fmaf(w3, c2.z, wg);
    float wb = w0 * c0.z; wb = fmaf(w1, c1.y, wb); wb = fmaf(w2, c2.x, wb); wb = fmaf(w3, c2.w, wb);

    // ---- 5-value butterfly reduction ----
    #pragma unroll
    for (int off = 16; off > 0; off >>= 1) {
        wsum += __shfl_xor_sync(FULL, wsum, off);
        wt   += __shfl_xor_sync(FULL, wt,   off);
        wr   += __shfl_xor_sync(FULL, wr,   off);
        wg   += __shfl_xor_sync(FULL, wg,   off);
        wb   += __shfl_xor_sync(FULL, wb,   off);
    }

    // ---- lanes 0-4 each write one output ----
    if (lane < 5) {
        if (lane < 3) {
            float bg = (1.0f - wsum) * BG_COLOR;
            float ch = (lane == 0) ? wr : ((lane == 1) ? wg : wb);
            out[3 * r + lane] = ch + bg;               // image r/g/b
        } else if (lane == 3) {
            out[(size_t)3 * N + r] = wt;               // depth
        } else {
            out[(size_t)4 * N + r] =
                fmaxf(wt - nearv, 0.0f) / (farv - nearv);  // depth_normalized
        }
    }
}

extern "C" void kernel_launch(void* const* d_in, const int* in_sizes, int n_in,
                              void* d_out, int out_size)
{
    const float* rays_o = (const float*)d_in[0];
    const float* rays_d = (const float*)d_in[1];
    const float* sigmas = (const float*)d_in[2];
    const float* rgbs   = (const float*)d_in[3];
    float* out = (float*)d_out;

    int N = in_sizes[0] / 3;   // rays_o is [N,3]

    int warps_per_block = 256 / 32;
    int blocks = (N + warps_per_block - 1) / warps_per_block;
    nerf_composite_kernel<<<blocks, 256>>>(rays_o, rays_d, sigmas, rgbs, out, N);
}

// round 14
// speedup vs baseline: 1.0213x; 1.0205x over previous
#include <cuda_runtime.h>
#include <math.h>

#define BOUND        1.0f
#define MIN_NEAR     0.2f
#define T_THRESH     1e-4f
#define BG_COLOR     1.0f
#define N_STEPS      128

// Body = R11 configuration (session best). One warp per ray; lane l owns
// samples 4l..4l+3 (lane-contiguous float4 -> 512B coalesced LDG.128, proven
// optimal R3/R5; all loads up-front proven necessary R8). Streaming loads,
// fast divides, difference-form weights, exclusive prefix via p/tot, plain
// 5-value butterfly epilogue. R14: 128-thread blocks (finest untested CTA
// granularity; 256 best so far, 512 regressed).
__global__ __launch_bounds__(128)
void nerf_composite_kernel(const float* __restrict__ rays_o,
                           const float* __restrict__ rays_d,
                           const float* __restrict__ sigmas,
                           const float* __restrict__ rgbs,
                           float* __restrict__ out,
                           int N)
{
    const unsigned FULL = 0xFFFFFFFFu;
    int w    = (blockIdx.x * blockDim.x + threadIdx.x) >> 5;
    int lane = threadIdx.x & 31;
    if (w >= N) return;
    const int r = w;

    // ---- 4 coalesced streaming LDG.128 per lane, all independent ----
    const float4* sig4 = (const float4*)(sigmas + (size_t)r * N_STEPS);
    const float4* rgb4 = (const float4*)(rgbs   + (size_t)r * (N_STEPS * 3));

    float4 s4 = __ldcs(&sig4[lane]);
    float4 c0 = __ldcs(&rgb4[3 * lane + 0]);
    float4 c1 = __ldcs(&rgb4[3 * lane + 1]);
    float4 c2 = __ldcs(&rgb4[3 * lane + 2]);
    // sample 0: (c0.x c0.y c0.z)  sample 1: (c0.w c1.x c1.y)
    // sample 2: (c1.z c1.w c2.x)  sample 3: (c2.y c2.z c2.w)

    // ---- slab test (fast divides; overlaps the loads) ----
    float ox = rays_o[3 * r + 0], oy = rays_o[3 * r + 1], oz = rays_o[3 * r + 2];
    float dx = rays_d[3 * r + 0], dy = rays_d[3 * r + 1], dz = rays_d[3 * r + 2];
    if (fabsf(dx) < 1e-8f) dx = 1e-8f;
    if (fabsf(dy) < 1e-8f) dy = 1e-8f;
    if (fabsf(dz) < 1e-8f) dz = 1e-8f;

    float t1x = __fdividef(-BOUND - ox, dx), t2x = __fdividef(BOUND - ox, dx);
    float t1y = __fdividef(-BOUND - oy, dy), t2y = __fdividef(BOUND - oy, dy);
    float t1z = __fdividef(-BOUND - oz, dz), t2z = __fdividef(BOUND - oz, dz);

    float nearv = fmaxf(fmaxf(fminf(t1x, t2x), fminf(t1y, t2y)), fminf(t1z, t2z));
    float farv  = fminf(fminf(fmaxf(t1x, t2x), fmaxf(t1y, t2y)), fmaxf(t1z, t2z));
    nearv = fmaxf(nearv, MIN_NEAR);
    farv  = fmaxf(farv, nearv + 1e-4f);

    const float delta = (farv - nearv) * (1.0f / (float)N_STEPS);
    const float nd = -delta;

    // ---- survival values (eps kept to match reference cumprod) ----
    float v0 = __expf(s4.x * nd) + 1e-10f;
    float v1 = __expf(s4.y * nd) + 1e-10f;
    float v2 = __expf(s4.z * nd) + 1e-10f;
    float v3 = __expf(s4.w * nd) + 1e-10f;

    // lane-local prefix products
    float lp1 = v0;
    float lp2 = v0 * v1;
    float lp3 = lp2 * v2;
    float tot = lp3 * v3;

    // warp inclusive scan-product over lane totals
    float p = tot;
    #pragma unroll
    for (int off = 1; off < 32; off <<= 1) {
        float q = __shfl_up_sync(FULL, p, off);
        if (lane >= off) p *= q;
    }
    // exclusive prefix without a shuffle: p includes this lane's tot
    float excl = __fdividef(p, tot);

    // exclusive transmittance; weights in difference form
    float T0 = excl;
    float T1 = excl * lp1;
    float T2 = excl * lp2;
    float T3 = excl * lp3;
    float T4 = p;

    float w0 = (T0 > T_THRESH) ? (T0 - T1) : 0.0f;
    float w1 = (T1 > T_THRESH) ? (T1 - T2) : 0.0f;
    float w2 = (T2 > T_THRESH) ? (T2 - T3) : 0.0f;
    float w3 = (T3 > T_THRESH) ? (T3 - T4) : 0.0f;

    // ---- accumulate (depth factored) ----
    float wsum = (w0 + w1) + (w2 + w3);
    float k = fmaf(2.0f, w2, w1);
    k = fmaf(3.0f, w3, k);
    float tbase = fmaf((float)(4 * lane) + 0.5f, delta, nearv);
    float wt = fmaf(delta, k, tbase * wsum);

    float wr = w0 * c0.x; wr = fmaf(w1, c0.w, wr); wr = fmaf(w2, c1.z, wr); wr = fmaf(w3, c2.y, wr);
    float wg = w0 * c0.y; wg = fmaf(w1, c1.x, wg); wg = fmaf(w2, c1.w, wg); wg = fmaf(w3, c2.z, wg);
    float wb = w0 * c0.z; wb = fmaf(w1, c1.y, wb); wb = fmaf(w2, c2.x, wb); wb = fmaf(w3, c2.w, wb);

    // ---- 5-value butterfly reduction ----
    #pragma unroll
    for (int off = 16; off > 0; off >>= 1) {
        wsum += __shfl_xor_sync(FULL, wsum, off);
        wt   += __shfl_xor_sync(FULL, wt,   off);
        wr   += __shfl_xor_sync(FULL, wr,   off);
        wg   += __shfl_xor_sync(FULL, wg,   off);
        wb   += __shfl_xor_sync(FULL, wb,   off);
    }

    // ---- lanes 0-4 each write one output ----
    if (lane < 5) {
        if (lane < 3) {
            float bg = (1.0f - wsum) * BG_COLOR;
            float ch = (lane == 0) ? wr : ((lane == 1) ? wg : wb);
            out[3 * r + lane] = ch + bg;               // image r/g/b
        } else if (lane == 3) {
            out[(size_t)3 * N + r] = wt;               // depth
        } else {
            out[(size_t)4 * N + r] =
                fmaxf(wt - nearv, 0.0f) / (farv - nearv);  // depth_normalized
        }
    }
}

extern "C" void kernel_launch(void* const* d_in, const int* in_sizes, int n_in,
                              void* d_out, int out_size)
{
    const float* rays_o = (const float*)d_in[0];
    const float* rays_d = (const float*)d_in[1];
    const float* sigmas = (const float*)d_in[2];
    const float* rgbs   = (const float*)d_in[3];
    float* out = (float*)d_out;

    int N = in_sizes[0] / 3;   // rays_o is [N,3]

    // one warp per ray; 4 warps (128 threads) per block
    int warps_per_block = 128 / 32;
    int blocks = (N + warps_per_block - 1) / warps_per_block;
    nerf_composite_kernel<<<blocks, 128>>>(rays_o, rays_d, sigmas, rgbs, out, N);
}

// round 15
// speedup vs baseline: 1.0257x; 1.0043x over previous
#include <cuda_runtime.h>
#include <math.h>

#define BOUND        1.0f
#define MIN_NEAR     0.2f
#define T_THRESH     1e-4f
#define BG_COLOR     1.0f
#define N_STEPS      128

// Body = R11 configuration (session best). One warp per ray; lane l owns
// samples 4l..4l+3 (lane-contiguous float4 -> 512B coalesced LDG.128, proven
// optimal R3/R5; all loads up-front proven necessary R8). Streaming loads,
// fast divides, difference-form weights, exclusive prefix via p/tot, plain
// 5-value butterfly epilogue. Block-size trend (ncu dur): 512=88.2 > 256=86.9
// > 128=84.2; R15 probes 64 (32 CTAs/SM, still 64-warp occupancy ceiling).
__global__ __launch_bounds__(64)
void nerf_composite_kernel(const float* __restrict__ rays_o,
                           const float* __restrict__ rays_d,
                           const float* __restrict__ sigmas,
                           const float* __restrict__ rgbs,
                           float* __restrict__ out,
                           int N)
{
    const unsigned FULL = 0xFFFFFFFFu;
    int w    = (blockIdx.x * blockDim.x + threadIdx.x) >> 5;
    int lane = threadIdx.x & 31;
    if (w >= N) return;
    const int r = w;

    // ---- 4 coalesced streaming LDG.128 per lane, all independent ----
    const float4* sig4 = (const float4*)(sigmas + (size_t)r * N_STEPS);
    const float4* rgb4 = (const float4*)(rgbs   + (size_t)r * (N_STEPS * 3));

    float4 s4 = __ldcs(&sig4[lane]);
    float4 c0 = __ldcs(&rgb4[3 * lane + 0]);
    float4 c1 = __ldcs(&rgb4[3 * lane + 1]);
    float4 c2 = __ldcs(&rgb4[3 * lane + 2]);
    // sample 0: (c0.x c0.y c0.z)  sample 1: (c0.w c1.x c1.y)
    // sample 2: (c1.z c1.w c2.x)  sample 3: (c2.y c2.z c2.w)

    // ---- slab test (fast divides; overlaps the loads) ----
    float ox = rays_o[3 * r + 0], oy = rays_o[3 * r + 1], oz = rays_o[3 * r + 2];
    float dx = rays_d[3 * r + 0], dy = rays_d[3 * r + 1], dz = rays_d[3 * r + 2];
    if (fabsf(dx) < 1e-8f) dx = 1e-8f;
    if (fabsf(dy) < 1e-8f) dy = 1e-8f;
    if (fabsf(dz) < 1e-8f) dz = 1e-8f;

    float t1x = __fdividef(-BOUND - ox, dx), t2x = __fdividef(BOUND - ox, dx);
    float t1y = __fdividef(-BOUND - oy, dy), t2y = __fdividef(BOUND - oy, dy);
    float t1z = __fdividef(-BOUND - oz, dz), t2z = __fdividef(BOUND - oz, dz);

    float nearv = fmaxf(fmaxf(fminf(t1x, t2x), fminf(t1y, t2y)), fminf(t1z, t2z));
    float farv  = fminf(fminf(fmaxf(t1x, t2x), fmaxf(t1y, t2y)), fmaxf(t1z, t2z));
    nearv = fmaxf(nearv, MIN_NEAR);
    farv  = fmaxf(farv, nearv + 1e-4f);

    const float delta = (farv - nearv) * (1.0f / (float)N_STEPS);
    const float nd = -delta;

    // ---- survival values (eps kept to match reference cumprod) ----
    float v0 = __expf(s4.x * nd) + 1e-10f;
    float v1 = __expf(s4.y * nd) + 1e-10f;
    float v2 = __expf(s4.z * nd) + 1e-10f;
    float v3 = __expf(s4.w * nd) + 1e-10f;

    // lane-local prefix products
    float lp1 = v0;
    float lp2 = v0 * v1;
    float lp3 = lp2 * v2;
    float tot = lp3 * v3;

    // warp inclusive scan-product over lane totals
    float p = tot;
    #pragma unroll
    for (int off = 1; off < 32; off <<= 1) {
        float q = __shfl_up_sync(FULL, p, off);
        if (lane >= off) p *= q;
    }
    // exclusive prefix without a shuffle: p includes this lane's tot
    float excl = __fdividef(p, tot);

    // exclusive transmittance; weights in difference form
    float T0 = excl;
    float T1 = excl * lp1;
    float T2 = excl * lp2;
    float T3 = excl * lp3;
    float T4 = p;

    float w0 = (T0 > T_THRESH) ? (T0 - T1) : 0.0f;
    float w1 = (T1 > T_THRESH) ? (T1 - T2) : 0.0f;
    float w2 = (T2 > T_THRESH) ? (T2 - T3) : 0.0f;
    float w3 = (T3 > T_THRESH) ? (T3 - T4) : 0.0f;

    // ---- accumulate (depth factored) ----
    float wsum = (w0 + w1) + (w2 + w3);
    float k = fmaf(2.0f, w2, w1);
    k = fmaf(3.0f, w3, k);
    float tbase = fmaf((float)(4 * lane) + 0.5f, delta, nearv);
    float wt = fmaf(delta, k, tbase * wsum);

    float wr = w0 * c0.x; wr = fmaf(w1, c0.w, wr); wr = fmaf(w2, c1.z, wr); wr = fmaf(w3, c2.y, wr);
    float wg = w0 * c0.y; wg = fmaf(w1, c1.x, wg); wg = fmaf(w2, c1.w, wg); wg = fmaf(w3, c2.z, wg);
    float wb = w0 * c0.z; wb = fmaf(w1, c1.y, wb); wb = fmaf(w2, c2.x, wb); wb = fmaf(w3, c2.w, wb);

    // ---- 5-value butterfly reduction ----
    #pragma unroll
    for (int off = 16; off > 0; off >>= 1) {
        wsum += __shfl_xor_sync(FULL, wsum, off);
        wt   += __shfl_xor_sync(FULL, wt,   off);
        wr   += __shfl_xor_sync(FULL, wr,   off);
        wg   += __shfl_xor_sync(FULL, wg,   off);
        wb   += __shfl_xor_sync(FULL, wb,   off);
    }

    // ---- lanes 0-4 each write one output ----
    if (lane < 5) {
        if (lane < 3) {
            float bg = (1.0f - wsum) * BG_COLOR;
            float ch = (lane == 0) ? wr : ((lane == 1) ? wg : wb);
            out[3 * r + lane] = ch + bg;               // image r/g/b
        } else if (lane == 3) {
            out[(size_t)3 * N + r] = wt;               // depth
        } else {
            out[(size_t)4 * N + r] =
                fmaxf(wt - nearv, 0.0f) / (farv - nearv);  // depth_normalized
        }
    }
}

extern "C" void kernel_launch(void* const* d_in, const int* in_sizes, int n_in,
                              void* d_out, int out_size)
{
    const float* rays_o = (const float*)d_in[0];
    const float* rays_d = (const float*)d_in[1];
    const float* sigmas = (const float*)d_in[2];
    const float* rgbs   = (const float*)d_in[3];
    float* out = (float*)d_out;

    int N = in_sizes[0] / 3;   // rays_o is [N,3]

    // one warp per ray; 2 warps (64 threads) per block
    int warps_per_block = 64 / 32;
    int blocks = (N + warps_per_block - 1) / warps_per_block;
    nerf_composite_kernel<<<blocks, 64>>>(rays_o, rays_d, sigmas, rgbs, out, N);
}